// round 1
// baseline (speedup 1.0000x reference)
#include <cuda_runtime.h>
#include <cuda_bf16.h>
#include <mma.h>

using namespace nvcuda;

// Problem constants (fixed by the dataset)
#define T_TOK 8192
#define H_DIM 2048
#define I_DIM 4096
#define E_NUM 8

#define SWIGLU_ALPHA 1.702f
#define SWIGLU_LIMIT 7.0f

// Scratch: gate / up intermediates (T x I each, fp32). __device__ globals are the
// sanctioned alloc-free scratch mechanism.
__device__ float g_gate[(size_t)T_TOK * I_DIM];
__device__ float g_up[(size_t)T_TOK * I_DIM];

// ---------------------------------------------------------------------------
// Generic grouped GEMM: C[M x N] = A[M x K] @ W[e][K x N]
// A rows are tokens; expert e chosen by the block's first row against offs[].
// tf32 wmma m16n16k8, BM=128 BN=128 BK=16, 8 warps (2x4), warp tile 64x32.
// ---------------------------------------------------------------------------
constexpr int BM = 128;
constexpr int BN = 128;
constexpr int BK = 16;
constexpr int LDA = BK + 8;   // 24, multiple of 8 for tf32 wmma ldm
constexpr int LDB = BN + 8;   // 136, multiple of 8

__global__ __launch_bounds__(256, 1)
void gemm_tf32(const float* __restrict__ A,
               const float* __restrict__ W,
               const int* __restrict__ offs,
               int K, int N,
               float* __restrict__ C)
{
    __shared__ float As[2][BM * LDA];
    __shared__ float Bs[2][BK * LDB];

    const int tid  = threadIdx.x;
    const int warp = tid >> 5;
    const int wm   = warp >> 2;   // 0..1
    const int wn   = warp & 3;    // 0..3

    const int row0 = blockIdx.y * BM;
    const int n0   = blockIdx.x * BN;

    // expert for this block (tiles never straddle group boundaries for the
    // dataset's offsets: multiples of 1024)
    int e = 0;
#pragma unroll
    for (int i = 0; i < E_NUM - 1; i++)
        if (row0 >= offs[i]) e = i + 1;

    const float* Ablk = A + (size_t)row0 * K;
    const float* Wblk = W + (size_t)e * K * N + n0;

    wmma::fragment<wmma::accumulator, 16, 16, 8, float> acc[4][2];
#pragma unroll
    for (int i = 0; i < 4; i++)
#pragma unroll
        for (int j = 0; j < 2; j++)
            wmma::fill_fragment(acc[i][j], 0.0f);

    const int ktiles = K / BK;

    float4 ra[2], rb[2];

    // ---- prologue: load tile 0 into buf 0 ----
#pragma unroll
    for (int s = 0; s < 2; s++) {
        int f   = tid + s * 256;           // 0..511
        int ar  = f >> 2;                  // A row 0..127
        int ac4 = f & 3;                   // A float4 col 0..3
        ra[s] = *reinterpret_cast<const float4*>(Ablk + (size_t)ar * K + ac4 * 4);
        int br  = f >> 5;                  // B k-row 0..15
        int bc4 = f & 31;                  // B float4 col 0..31
        rb[s] = *reinterpret_cast<const float4*>(Wblk + (size_t)br * N + bc4 * 4);
    }
#pragma unroll
    for (int s = 0; s < 2; s++) {
        int f = tid + s * 256;
        int ar = f >> 2, ac4 = f & 3;
        *reinterpret_cast<float4*>(&As[0][ar * LDA + ac4 * 4]) = ra[s];
        int br = f >> 5, bc4 = f & 31;
        *reinterpret_cast<float4*>(&Bs[0][br * LDB + bc4 * 4]) = rb[s];
    }
    __syncthreads();

    for (int kt = 0; kt < ktiles; ++kt) {
        const int buf = kt & 1;

        // issue next tile's global loads early (overlap with compute)
        if (kt + 1 < ktiles) {
            const int k0 = (kt + 1) * BK;
#pragma unroll
            for (int s = 0; s < 2; s++) {
                int f   = tid + s * 256;
                int ar  = f >> 2;
                int ac4 = f & 3;
                ra[s] = *reinterpret_cast<const float4*>(Ablk + (size_t)ar * K + k0 + ac4 * 4);
                int br  = f >> 5;
                int bc4 = f & 31;
                rb[s] = *reinterpret_cast<const float4*>(Wblk + (size_t)(k0 + br) * N + bc4 * 4);
            }
        }

        // compute on smem[buf]
#pragma unroll
        for (int ks = 0; ks < 2; ++ks) {
            wmma::fragment<wmma::matrix_a, 16, 16, 8, wmma::precision::tf32, wmma::row_major> af[4];
            wmma::fragment<wmma::matrix_b, 16, 16, 8, wmma::precision::tf32, wmma::row_major> bf[2];
#pragma unroll
            for (int mm = 0; mm < 4; mm++) {
                wmma::load_matrix_sync(af[mm], &As[buf][(wm * 64 + mm * 16) * LDA + ks * 8], LDA);
#pragma unroll
                for (int t = 0; t < af[mm].num_elements; t++)
                    af[mm].x[t] = wmma::__float_to_tf32(af[mm].x[t]);
            }
#pragma unroll
            for (int nn = 0; nn < 2; nn++) {
                wmma::load_matrix_sync(bf[nn], &Bs[buf][(ks * 8) * LDB + wn * 32 + nn * 16], LDB);
#pragma unroll
                for (int t = 0; t < bf[nn].num_elements; t++)
                    bf[nn].x[t] = wmma::__float_to_tf32(bf[nn].x[t]);
            }
#pragma unroll
            for (int mm = 0; mm < 4; mm++)
#pragma unroll
                for (int nn = 0; nn < 2; nn++)
                    wmma::mma_sync(acc[mm][nn], af[mm], bf[nn], acc[mm][nn]);
        }

        __syncthreads();
        if (kt + 1 < ktiles) {
#pragma unroll
            for (int s = 0; s < 2; s++) {
                int f = tid + s * 256;
                int ar = f >> 2, ac4 = f & 3;
                *reinterpret_cast<float4*>(&As[buf ^ 1][ar * LDA + ac4 * 4]) = ra[s];
                int br = f >> 5, bc4 = f & 31;
                *reinterpret_cast<float4*>(&Bs[buf ^ 1][br * LDB + bc4 * 4]) = rb[s];
            }
            __syncthreads();
        }
    }

    // epilogue: store raw accumulators (bias handled by downstream kernels)
#pragma unroll
    for (int mm = 0; mm < 4; mm++)
#pragma unroll
        for (int nn = 0; nn < 2; nn++) {
            float* cp = C + (size_t)(row0 + wm * 64 + mm * 16) * N + n0 + wn * 32 + nn * 16;
            wmma::store_matrix_sync(cp, acc[mm][nn], N, wmma::mem_row_major);
        }
}

// ---------------------------------------------------------------------------
// Fused bias + swiglu activation: act[t,i] = (clip(up+ub,-7,7)+1) * glu
//   glu = g * sigmoid(1.702 g),  g = min(gate+gb, 7)
// Writes result in place into g_gate.
// ---------------------------------------------------------------------------
__global__ __launch_bounds__(256)
void act_kernel(const float* __restrict__ gate,
                const float* __restrict__ up,
                const float* __restrict__ gate_b,
                const float* __restrict__ up_b,
                const int* __restrict__ offs,
                float* __restrict__ out)
{
    size_t v = (size_t)blockIdx.x * blockDim.x + threadIdx.x;   // float4 index
    size_t base = v * 4;
    if (base >= (size_t)T_TOK * I_DIM) return;
    int t = (int)(base / I_DIM);
    int i = (int)(base % I_DIM);

    int e = 0;
#pragma unroll
    for (int k = 0; k < E_NUM - 1; k++)
        if (t >= offs[k]) e = k + 1;

    float4 g4  = *reinterpret_cast<const float4*>(gate + base);
    float4 u4  = *reinterpret_cast<const float4*>(up + base);
    float4 gb4 = *reinterpret_cast<const float4*>(gate_b + (size_t)e * I_DIM + i);
    float4 ub4 = *reinterpret_cast<const float4*>(up_b + (size_t)e * I_DIM + i);

    float go[4];
    const float* gp = &g4.x; const float* up_ = &u4.x;
    const float* gbp = &gb4.x; const float* ubp = &ub4.x;
#pragma unroll
    for (int k = 0; k < 4; k++) {
        float g = gp[k] + gbp[k];
        float u = up_[k] + ubp[k];
        g = fminf(g, SWIGLU_LIMIT);
        u = fminf(fmaxf(u, -SWIGLU_LIMIT), SWIGLU_LIMIT);
        float sig = 1.0f / (1.0f + expf(-SWIGLU_ALPHA * g));
        float glu = g * sig;
        go[k] = (u + 1.0f) * glu;
    }
    float4 o4 = make_float4(go[0], go[1], go[2], go[3]);
    *reinterpret_cast<float4*>(out + base) = o4;
}

// ---------------------------------------------------------------------------
// Final bias add: out[t,h] += down_b[e,h]
// ---------------------------------------------------------------------------
__global__ __launch_bounds__(256)
void bias_out_kernel(float* __restrict__ out,
                     const float* __restrict__ down_b,
                     const int* __restrict__ offs)
{
    size_t v = (size_t)blockIdx.x * blockDim.x + threadIdx.x;   // float4 index
    size_t base = v * 4;
    if (base >= (size_t)T_TOK * H_DIM) return;
    int t = (int)(base / H_DIM);
    int h = (int)(base % H_DIM);

    int e = 0;
#pragma unroll
    for (int k = 0; k < E_NUM - 1; k++)
        if (t >= offs[k]) e = k + 1;

    float4 o4 = *reinterpret_cast<float4*>(out + base);
    float4 b4 = *reinterpret_cast<const float4*>(down_b + (size_t)e * H_DIM + h);
    o4.x += b4.x; o4.y += b4.y; o4.z += b4.z; o4.w += b4.w;
    *reinterpret_cast<float4*>(out + base) = o4;
}

// ---------------------------------------------------------------------------
// Launch
// ---------------------------------------------------------------------------
extern "C" void kernel_launch(void* const* d_in, const int* in_sizes, int n_in,
                              void* d_out, int out_size)
{
    const float* x       = (const float*)d_in[0];
    const int*   offs    = (const int*)d_in[1];
    const float* gate_w  = (const float*)d_in[2];
    const float* up_w    = (const float*)d_in[3];
    const float* down_w  = (const float*)d_in[4];
    const float* gate_b  = (const float*)d_in[5];
    const float* up_b    = (const float*)d_in[6];
    const float* down_b  = (const float*)d_in[7];
    float* out = (float*)d_out;

    float* pg = nullptr;
    float* pu = nullptr;
    cudaGetSymbolAddress((void**)&pg, g_gate);
    cudaGetSymbolAddress((void**)&pu, g_up);

    dim3 block(256);

    // gate = x @ gate_w[e]   (K=H, N=I)
    {
        dim3 grid(I_DIM / BN, T_TOK / BM);
        gemm_tf32<<<grid, block>>>(x, gate_w, offs, H_DIM, I_DIM, pg);
    }
    // up = x @ up_w[e]
    {
        dim3 grid(I_DIM / BN, T_TOK / BM);
        gemm_tf32<<<grid, block>>>(x, up_w, offs, H_DIM, I_DIM, pu);
    }
    // activated = swiglu(gate + gb, up + ub)  -> in place into g_gate
    {
        size_t n4 = (size_t)T_TOK * I_DIM / 4;
        dim3 grid((unsigned)((n4 + 255) / 256));
        act_kernel<<<grid, block>>>(pg, pu, gate_b, up_b, offs, pg);
    }
    // out = activated @ down_w[e]   (K=I, N=H)
    {
        dim3 grid(H_DIM / BN, T_TOK / BM);
        gemm_tf32<<<grid, block>>>(pg, down_w, offs, I_DIM, H_DIM, out);
    }
    // out += down_b[e]
    {
        size_t n4 = (size_t)T_TOK * H_DIM / 4;
        dim3 grid((unsigned)((n4 + 255) / 256));
        bias_out_kernel<<<grid, block>>>(out, down_b, offs);
    }
}

// round 2
// speedup vs baseline: 1.0003x; 1.0003x over previous
#include <cuda_runtime.h>
#include <cuda_bf16.h>
#include <mma.h>

using namespace nvcuda;

// Problem constants (fixed by the dataset)
#define T_TOK 8192
#define H_DIM 2048
#define I_DIM 4096
#define E_NUM 8

#define SWIGLU_ALPHA 1.702f
#define SWIGLU_LIMIT 7.0f

// Scratch: gate / up intermediates (T x I each, fp32). __device__ globals are the
// sanctioned alloc-free scratch mechanism.
__device__ float g_gate[(size_t)T_TOK * I_DIM];
__device__ float g_up[(size_t)T_TOK * I_DIM];

// ---------------------------------------------------------------------------
// Generic grouped GEMM: C[M x N] = A[M x K] @ W[e][K x N]
// A rows are tokens; expert e chosen by the block's first row against offs[].
// tf32 wmma m16n16k8, BM=128 BN=128 BK=16, 8 warps (2x4), warp tile 64x32.
// ---------------------------------------------------------------------------
constexpr int BM = 128;
constexpr int BN = 128;
constexpr int BK = 16;
constexpr int LDA = BK + 8;   // 24, multiple of 8 for tf32 wmma ldm
constexpr int LDB = BN + 8;   // 136, multiple of 8

__global__ __launch_bounds__(256, 1)
void gemm_tf32(const float* __restrict__ A,
               const float* __restrict__ W,
               const int* __restrict__ offs,
               int K, int N,
               float* __restrict__ C)
{
    __shared__ float As[2][BM * LDA];
    __shared__ float Bs[2][BK * LDB];

    const int tid  = threadIdx.x;
    const int warp = tid >> 5;
    const int wm   = warp >> 2;   // 0..1
    const int wn   = warp & 3;    // 0..3

    const int row0 = blockIdx.y * BM;
    const int n0   = blockIdx.x * BN;

    // expert for this block (tiles never straddle group boundaries for the
    // dataset's offsets: multiples of 1024)
    int e = 0;
#pragma unroll
    for (int i = 0; i < E_NUM - 1; i++)
        if (row0 >= offs[i]) e = i + 1;

    const float* Ablk = A + (size_t)row0 * K;
    const float* Wblk = W + (size_t)e * K * N + n0;

    wmma::fragment<wmma::accumulator, 16, 16, 8, float> acc[4][2];
#pragma unroll
    for (int i = 0; i < 4; i++)
#pragma unroll
        for (int j = 0; j < 2; j++)
            wmma::fill_fragment(acc[i][j], 0.0f);

    const int ktiles = K / BK;

    float4 ra[2], rb[2];

    // ---- prologue: load tile 0 into buf 0 ----
#pragma unroll
    for (int s = 0; s < 2; s++) {
        int f   = tid + s * 256;           // 0..511
        int ar  = f >> 2;                  // A row 0..127
        int ac4 = f & 3;                   // A float4 col 0..3
        ra[s] = *reinterpret_cast<const float4*>(Ablk + (size_t)ar * K + ac4 * 4);
        int br  = f >> 5;                  // B k-row 0..15
        int bc4 = f & 31;                  // B float4 col 0..31
        rb[s] = *reinterpret_cast<const float4*>(Wblk + (size_t)br * N + bc4 * 4);
    }
#pragma unroll
    for (int s = 0; s < 2; s++) {
        int f = tid + s * 256;
        int ar = f >> 2, ac4 = f & 3;
        *reinterpret_cast<float4*>(&As[0][ar * LDA + ac4 * 4]) = ra[s];
        int br = f >> 5, bc4 = f & 31;
        *reinterpret_cast<float4*>(&Bs[0][br * LDB + bc4 * 4]) = rb[s];
    }
    __syncthreads();

    for (int kt = 0; kt < ktiles; ++kt) {
        const int buf = kt & 1;

        // issue next tile's global loads early (overlap with compute)
        if (kt + 1 < ktiles) {
            const int k0 = (kt + 1) * BK;
#pragma unroll
            for (int s = 0; s < 2; s++) {
                int f   = tid + s * 256;
                int ar  = f >> 2;
                int ac4 = f & 3;
                ra[s] = *reinterpret_cast<const float4*>(Ablk + (size_t)ar * K + k0 + ac4 * 4);
                int br  = f >> 5;
                int bc4 = f & 31;
                rb[s] = *reinterpret_cast<const float4*>(Wblk + (size_t)(k0 + br) * N + bc4 * 4);
            }
        }

        // compute on smem[buf]
#pragma unroll
        for (int ks = 0; ks < 2; ++ks) {
            wmma::fragment<wmma::matrix_a, 16, 16, 8, wmma::precision::tf32, wmma::row_major> af[4];
            wmma::fragment<wmma::matrix_b, 16, 16, 8, wmma::precision::tf32, wmma::row_major> bf[2];
#pragma unroll
            for (int mm = 0; mm < 4; mm++) {
                wmma::load_matrix_sync(af[mm], &As[buf][(wm * 64 + mm * 16) * LDA + ks * 8], LDA);
#pragma unroll
                for (int t = 0; t < af[mm].num_elements; t++)
                    af[mm].x[t] = wmma::__float_to_tf32(af[mm].x[t]);
            }
#pragma unroll
            for (int nn = 0; nn < 2; nn++) {
                wmma::load_matrix_sync(bf[nn], &Bs[buf][(ks * 8) * LDB + wn * 32 + nn * 16], LDB);
#pragma unroll
                for (int t = 0; t < bf[nn].num_elements; t++)
                    bf[nn].x[t] = wmma::__float_to_tf32(bf[nn].x[t]);
            }
#pragma unroll
            for (int mm = 0; mm < 4; mm++)
#pragma unroll
                for (int nn = 0; nn < 2; nn++)
                    wmma::mma_sync(acc[mm][nn], af[mm], bf[nn], acc[mm][nn]);
        }

        __syncthreads();
        if (kt + 1 < ktiles) {
#pragma unroll
            for (int s = 0; s < 2; s++) {
                int f = tid + s * 256;
                int ar = f >> 2, ac4 = f & 3;
                *reinterpret_cast<float4*>(&As[buf ^ 1][ar * LDA + ac4 * 4]) = ra[s];
                int br = f >> 5, bc4 = f & 31;
                *reinterpret_cast<float4*>(&Bs[buf ^ 1][br * LDB + bc4 * 4]) = rb[s];
            }
            __syncthreads();
        }
    }

    // epilogue: store raw accumulators (bias handled by downstream kernels)
#pragma unroll
    for (int mm = 0; mm < 4; mm++)
#pragma unroll
        for (int nn = 0; nn < 2; nn++) {
            float* cp = C + (size_t)(row0 + wm * 64 + mm * 16) * N + n0 + wn * 32 + nn * 16;
            wmma::store_matrix_sync(cp, acc[mm][nn], N, wmma::mem_row_major);
        }
}

// ---------------------------------------------------------------------------
// Fused bias + swiglu activation: act[t,i] = (clip(up+ub,-7,7)+1) * glu
//   glu = g * sigmoid(1.702 g),  g = min(gate+gb, 7)
// Writes result in place into g_gate.
// ---------------------------------------------------------------------------
__global__ __launch_bounds__(256)
void act_kernel(const float* __restrict__ gate,
                const float* __restrict__ up,
                const float* __restrict__ gate_b,
                const float* __restrict__ up_b,
                const int* __restrict__ offs,
                float* __restrict__ out)
{
    size_t v = (size_t)blockIdx.x * blockDim.x + threadIdx.x;   // float4 index
    size_t base = v * 4;
    if (base >= (size_t)T_TOK * I_DIM) return;
    int t = (int)(base / I_DIM);
    int i = (int)(base % I_DIM);

    int e = 0;
#pragma unroll
    for (int k = 0; k < E_NUM - 1; k++)
        if (t >= offs[k]) e = k + 1;

    float4 g4  = *reinterpret_cast<const float4*>(gate + base);
    float4 u4  = *reinterpret_cast<const float4*>(up + base);
    float4 gb4 = *reinterpret_cast<const float4*>(gate_b + (size_t)e * I_DIM + i);
    float4 ub4 = *reinterpret_cast<const float4*>(up_b + (size_t)e * I_DIM + i);

    float go[4];
    const float* gp = &g4.x; const float* up_ = &u4.x;
    const float* gbp = &gb4.x; const float* ubp = &ub4.x;
#pragma unroll
    for (int k = 0; k < 4; k++) {
        float g = gp[k] + gbp[k];
        float u = up_[k] + ubp[k];
        g = fminf(g, SWIGLU_LIMIT);
        u = fminf(fmaxf(u, -SWIGLU_LIMIT), SWIGLU_LIMIT);
        float sig = 1.0f / (1.0f + expf(-SWIGLU_ALPHA * g));
        float glu = g * sig;
        go[k] = (u + 1.0f) * glu;
    }
    float4 o4 = make_float4(go[0], go[1], go[2], go[3]);
    *reinterpret_cast<float4*>(out + base) = o4;
}

// ---------------------------------------------------------------------------
// Final bias add: out[t,h] += down_b[e,h]
// ---------------------------------------------------------------------------
__global__ __launch_bounds__(256)
void bias_out_kernel(float* __restrict__ out,
                     const float* __restrict__ down_b,
                     const int* __restrict__ offs)
{
    size_t v = (size_t)blockIdx.x * blockDim.x + threadIdx.x;   // float4 index
    size_t base = v * 4;
    if (base >= (size_t)T_TOK * H_DIM) return;
    int t = (int)(base / H_DIM);
    int h = (int)(base % H_DIM);

    int e = 0;
#pragma unroll
    for (int k = 0; k < E_NUM - 1; k++)
        if (t >= offs[k]) e = k + 1;

    float4 o4 = *reinterpret_cast<float4*>(out + base);
    float4 b4 = *reinterpret_cast<const float4*>(down_b + (size_t)e * H_DIM + h);
    o4.x += b4.x; o4.y += b4.y; o4.z += b4.z; o4.w += b4.w;
    *reinterpret_cast<float4*>(out + base) = o4;
}

// ---------------------------------------------------------------------------
// Launch
// ---------------------------------------------------------------------------
extern "C" void kernel_launch(void* const* d_in, const int* in_sizes, int n_in,
                              void* d_out, int out_size)
{
    const float* x       = (const float*)d_in[0];
    const int*   offs    = (const int*)d_in[1];
    const float* gate_w  = (const float*)d_in[2];
    const float* up_w    = (const float*)d_in[3];
    const float* down_w  = (const float*)d_in[4];
    const float* gate_b  = (const float*)d_in[5];
    const float* up_b    = (const float*)d_in[6];
    const float* down_b  = (const float*)d_in[7];
    float* out = (float*)d_out;

    float* pg = nullptr;
    float* pu = nullptr;
    cudaGetSymbolAddress((void**)&pg, g_gate);
    cudaGetSymbolAddress((void**)&pu, g_up);

    dim3 block(256);

    // gate = x @ gate_w[e]   (K=H, N=I)
    {
        dim3 grid(I_DIM / BN, T_TOK / BM);
        gemm_tf32<<<grid, block>>>(x, gate_w, offs, H_DIM, I_DIM, pg);
    }
    // up = x @ up_w[e]
    {
        dim3 grid(I_DIM / BN, T_TOK / BM);
        gemm_tf32<<<grid, block>>>(x, up_w, offs, H_DIM, I_DIM, pu);
    }
    // activated = swiglu(gate + gb, up + ub)  -> in place into g_gate
    {
        size_t n4 = (size_t)T_TOK * I_DIM / 4;
        dim3 grid((unsigned)((n4 + 255) / 256));
        act_kernel<<<grid, block>>>(pg, pu, gate_b, up_b, offs, pg);
    }
    // out = activated @ down_w[e]   (K=I, N=H)
    {
        dim3 grid(H_DIM / BN, T_TOK / BM);
        gemm_tf32<<<grid, block>>>(pg, down_w, offs, I_DIM, H_DIM, out);
    }
    // out += down_b[e]
    {
        size_t n4 = (size_t)T_TOK * H_DIM / 4;
        dim3 grid((unsigned)((n4 + 255) / 256));
        bias_out_kernel<<<grid, block>>>(out, down_b, offs);
    }
}

// round 4
// speedup vs baseline: 3.1980x; 3.1970x over previous
#include <cuda_runtime.h>
#include <cstdint>

#define T_TOK 8192
#define H_DIM 2048
#define I_DIM 4096
#define E_NUM 8
#define SWIGLU_ALPHA 1.702f
#define SWIGLU_LIMIT 7.0f

// Scratch: activated intermediate (T x I fp32)
__device__ float g_act[(size_t)T_TOK * I_DIM];

// ---------------------------------------------------------------------------
// Helpers
// ---------------------------------------------------------------------------
__device__ __forceinline__ uint32_t smem_u32(const void* p) {
    uint32_t a;
    asm("{ .reg .u64 t; cvta.to.shared.u64 t, %1; cvt.u32.u64 %0, t; }" : "=r"(a) : "l"(p));
    return a;
}
__device__ __forceinline__ uint32_t f2tf32(float v) {
    uint32_t r;
    asm("cvt.rna.tf32.f32 %0, %1;" : "=r"(r) : "f"(v));
    return r;
}
__device__ __forceinline__ void mma8(float c[4],
                                     uint32_t a0, uint32_t a1, uint32_t a2, uint32_t a3,
                                     uint32_t b0, uint32_t b1) {
    asm("mma.sync.aligned.m16n8k8.row.col.f32.tf32.tf32.f32 "
        "{%0,%1,%2,%3}, {%4,%5,%6,%7}, {%8,%9}, {%0,%1,%2,%3};"
        : "+f"(c[0]), "+f"(c[1]), "+f"(c[2]), "+f"(c[3])
        : "r"(a0), "r"(a1), "r"(a2), "r"(a3), "r"(b0), "r"(b1));
}
#define CP16(dst, src) \
    asm volatile("cp.async.cg.shared.global [%0], [%1], 16;" :: "r"(dst), "l"(src))
#define CP_COMMIT() asm volatile("cp.async.commit_group;")
#define CP_WAIT1()  asm volatile("cp.async.wait_group 1;")

__device__ __forceinline__ float swiglu(float g, float u) {
    g = fminf(g, SWIGLU_LIMIT);
    u = fminf(fmaxf(u, -SWIGLU_LIMIT), SWIGLU_LIMIT);
    float sig = 1.0f / (1.0f + __expf(-SWIGLU_ALPHA * g));
    return (u + 1.0f) * g * sig;
}

// Tile geometry (both kernels): CTA 128x128, BK=32, 8 warps (2x4), warp 64x32
constexpr int APAD = 36;    // conflict-free A reads: bank = (4r+c)%32
constexpr int BPAD = 136;   // conflict-free B reads: bank = (8k+n)%32
constexpr int ABYTES = 128 * APAD * 4;   // 18432
constexpr int BBYTES = 32 * BPAD * 4;    // 17408

// ===========================================================================
// Fused gate+up GEMM + bias + swiglu -> g_act
// C tile 128(M tokens) x 128(N intermediate) for BOTH gate and up
// ===========================================================================
constexpr int STG12 = 3;
constexpr int STAGE12 = ABYTES + 2 * BBYTES;   // 53248
constexpr int DYN12 = STG12 * STAGE12;          // 159744

__global__ __launch_bounds__(256, 1)
void gemm12(const float* __restrict__ x,
            const float* __restrict__ gw,
            const float* __restrict__ uw,
            const float* __restrict__ gb,
            const float* __restrict__ ub,
            const int* __restrict__ offs,
            float* __restrict__ act)
{
    extern __shared__ float sm[];
    const uint32_t sbase = smem_u32(sm);
    const int tid = threadIdx.x, lane = tid & 31, warp = tid >> 5;
    const int wm = warp >> 2, wn = warp & 3;
    const int gid = lane >> 2, tig = lane & 3;
    const int n0 = blockIdx.x * 128, m0 = blockIdx.y * 128;

    int e = 0;
#pragma unroll
    for (int i = 0; i < E_NUM - 1; i++)
        if (m0 >= offs[i]) e = i + 1;

    const float* xa  = x + (size_t)m0 * H_DIM;
    const float* gwa = gw + (size_t)e * H_DIM * I_DIM + n0;
    const float* uwa = uw + (size_t)e * H_DIM * I_DIM + n0;

    auto issue = [&](int it, int s) {
        const uint32_t sa = sbase + s * STAGE12;
        const int k0 = it * 32;
#pragma unroll
        for (int j = 0; j < 4; j++) {
            int idx = tid + 256 * j;
            int r = idx >> 3, c4 = idx & 7;
            CP16(sa + (uint32_t)(r * APAD + c4 * 4) * 4,
                 xa + (size_t)r * H_DIM + k0 + c4 * 4);
        }
        const uint32_t sg = sa + ABYTES, su = sa + ABYTES + BBYTES;
#pragma unroll
        for (int j = 0; j < 4; j++) {
            int idx = tid + 256 * j;
            int r = idx >> 5, c4 = idx & 31;
            uint32_t off = (uint32_t)(r * BPAD + c4 * 4) * 4;
            CP16(sg + off, gwa + (size_t)(k0 + r) * I_DIM + c4 * 4);
            CP16(su + off, uwa + (size_t)(k0 + r) * I_DIM + c4 * 4);
        }
        CP_COMMIT();
    };

    float cg[4][4][4] = {}, cu[4][4][4] = {};

    issue(0, 0);
    issue(1, 1);

    const int NIT = H_DIM / 32;   // 64
    for (int it = 0; it < NIT; ++it) {
        const int s = it % STG12;
        CP_WAIT1();
        __syncthreads();

        const float* A  = sm + s * (STAGE12 / 4);
        const float* Bg = A + ABYTES / 4;
        const float* Bu = Bg + BBYTES / 4;

#pragma unroll
        for (int ks = 0; ks < 4; ++ks) {
            uint32_t a[4][4];
#pragma unroll
            for (int mf = 0; mf < 4; mf++) {
                const float* ap = A + (wm * 64 + mf * 16 + gid) * APAD + ks * 8 + tig;
                a[mf][0] = f2tf32(ap[0]);
                a[mf][1] = f2tf32(ap[8 * APAD]);
                a[mf][2] = f2tf32(ap[4]);
                a[mf][3] = f2tf32(ap[8 * APAD + 4]);
            }
#pragma unroll
            for (int nf = 0; nf < 4; nf++) {
                const int c = wn * 32 + nf * 8 + gid;
                const float* bp = Bg + (ks * 8 + tig) * BPAD + c;
                uint32_t b0 = f2tf32(bp[0]), b1 = f2tf32(bp[4 * BPAD]);
                const float* up = Bu + (ks * 8 + tig) * BPAD + c;
                uint32_t u0 = f2tf32(up[0]), u1 = f2tf32(up[4 * BPAD]);
#pragma unroll
                for (int mf = 0; mf < 4; mf++) {
                    mma8(cg[mf][nf], a[mf][0], a[mf][1], a[mf][2], a[mf][3], b0, b1);
                    mma8(cu[mf][nf], a[mf][0], a[mf][1], a[mf][2], a[mf][3], u0, u1);
                }
            }
        }
        if (it + 2 < NIT) issue(it + 2, (it + 2) % STG12);
        else CP_COMMIT();
    }

    // Epilogue: bias + swiglu -> act
#pragma unroll
    for (int nf = 0; nf < 4; nf++) {
        const int c0 = n0 + wn * 32 + nf * 8 + 2 * tig;
        const float2 gbv = *reinterpret_cast<const float2*>(gb + (size_t)e * I_DIM + c0);
        const float2 ubv = *reinterpret_cast<const float2*>(ub + (size_t)e * I_DIM + c0);
#pragma unroll
        for (int mf = 0; mf < 4; mf++) {
            const int r0 = m0 + wm * 64 + mf * 16 + gid;
            float2 o0, o1;
            o0.x = swiglu(cg[mf][nf][0] + gbv.x, cu[mf][nf][0] + ubv.x);
            o0.y = swiglu(cg[mf][nf][1] + gbv.y, cu[mf][nf][1] + ubv.y);
            o1.x = swiglu(cg[mf][nf][2] + gbv.x, cu[mf][nf][2] + ubv.x);
            o1.y = swiglu(cg[mf][nf][3] + gbv.y, cu[mf][nf][3] + ubv.y);
            *reinterpret_cast<float2*>(act + (size_t)r0 * I_DIM + c0) = o0;
            *reinterpret_cast<float2*>(act + (size_t)(r0 + 8) * I_DIM + c0) = o1;
        }
    }
}

// ===========================================================================
// Down GEMM + bias -> out
// ===========================================================================
constexpr int STG3 = 4;
constexpr int STAGE3 = ABYTES + BBYTES;   // 35840
constexpr int DYN3 = STG3 * STAGE3;        // 143360

__global__ __launch_bounds__(256, 1)
void gemm3(const float* __restrict__ act,
           const float* __restrict__ dw,
           const float* __restrict__ db,
           const int* __restrict__ offs,
           float* __restrict__ out)
{
    extern __shared__ float sm[];
    const uint32_t sbase = smem_u32(sm);
    const int tid = threadIdx.x, lane = tid & 31, warp = tid >> 5;
    const int wm = warp >> 2, wn = warp & 3;
    const int gid = lane >> 2, tig = lane & 3;
    const int n0 = blockIdx.x * 128, m0 = blockIdx.y * 128;

    int e = 0;
#pragma unroll
    for (int i = 0; i < E_NUM - 1; i++)
        if (m0 >= offs[i]) e = i + 1;

    const float* aa  = act + (size_t)m0 * I_DIM;
    const float* dwa = dw + (size_t)e * I_DIM * H_DIM + n0;

    auto issue = [&](int it, int s) {
        const uint32_t sa = sbase + s * STAGE3;
        const int k0 = it * 32;
#pragma unroll
        for (int j = 0; j < 4; j++) {
            int idx = tid + 256 * j;
            int r = idx >> 3, c4 = idx & 7;
            CP16(sa + (uint32_t)(r * APAD + c4 * 4) * 4,
                 aa + (size_t)r * I_DIM + k0 + c4 * 4);
        }
        const uint32_t sb = sa + ABYTES;
#pragma unroll
        for (int j = 0; j < 4; j++) {
            int idx = tid + 256 * j;
            int r = idx >> 5, c4 = idx & 31;
            CP16(sb + (uint32_t)(r * BPAD + c4 * 4) * 4,
                 dwa + (size_t)(k0 + r) * H_DIM + c4 * 4);
        }
        CP_COMMIT();
    };

    float cc[4][4][4] = {};

    issue(0, 0);
    issue(1, 1);

    const int NIT = I_DIM / 32;   // 128
    for (int it = 0; it < NIT; ++it) {
        const int s = it % STG3;
        CP_WAIT1();
        __syncthreads();

        const float* A = sm + s * (STAGE3 / 4);
        const float* B = A + ABYTES / 4;

#pragma unroll
        for (int ks = 0; ks < 4; ++ks) {
            uint32_t a[4][4];
#pragma unroll
            for (int mf = 0; mf < 4; mf++) {
                const float* ap = A + (wm * 64 + mf * 16 + gid) * APAD + ks * 8 + tig;
                a[mf][0] = f2tf32(ap[0]);
                a[mf][1] = f2tf32(ap[8 * APAD]);
                a[mf][2] = f2tf32(ap[4]);
                a[mf][3] = f2tf32(ap[8 * APAD + 4]);
            }
#pragma unroll
            for (int nf = 0; nf < 4; nf++) {
                const int c = wn * 32 + nf * 8 + gid;
                const float* bp = B + (ks * 8 + tig) * BPAD + c;
                uint32_t b0 = f2tf32(bp[0]), b1 = f2tf32(bp[4 * BPAD]);
#pragma unroll
                for (int mf = 0; mf < 4; mf++)
                    mma8(cc[mf][nf], a[mf][0], a[mf][1], a[mf][2], a[mf][3], b0, b1);
            }
        }
        if (it + 2 < NIT) issue(it + 2, (it + 2) % STG3);
        else CP_COMMIT();
    }

    // Epilogue: + down_b -> out
#pragma unroll
    for (int nf = 0; nf < 4; nf++) {
        const int c0 = n0 + wn * 32 + nf * 8 + 2 * tig;
        const float2 bv = *reinterpret_cast<const float2*>(db + (size_t)e * H_DIM + c0);
#pragma unroll
        for (int mf = 0; mf < 4; mf++) {
            const int r0 = m0 + wm * 64 + mf * 16 + gid;
            float2 o0, o1;
            o0.x = cc[mf][nf][0] + bv.x;
            o0.y = cc[mf][nf][1] + bv.y;
            o1.x = cc[mf][nf][2] + bv.x;
            o1.y = cc[mf][nf][3] + bv.y;
            *reinterpret_cast<float2*>(out + (size_t)r0 * H_DIM + c0) = o0;
            *reinterpret_cast<float2*>(out + (size_t)(r0 + 8) * H_DIM + c0) = o1;
        }
    }
}

// ===========================================================================
// Launch
// ===========================================================================
extern "C" void kernel_launch(void* const* d_in, const int* in_sizes, int n_in,
                              void* d_out, int out_size)
{
    const float* x      = (const float*)d_in[0];
    const int*   offs   = (const int*)d_in[1];
    const float* gate_w = (const float*)d_in[2];
    const float* up_w   = (const float*)d_in[3];
    const float* down_w = (const float*)d_in[4];
    const float* gate_b = (const float*)d_in[5];
    const float* up_b   = (const float*)d_in[6];
    const float* down_b = (const float*)d_in[7];
    float* out = (float*)d_out;

    float* pact = nullptr;
    cudaGetSymbolAddress((void**)&pact, g_act);

    static bool attr_set = false;
    cudaFuncSetAttribute(gemm12, cudaFuncAttributeMaxDynamicSharedMemorySize, DYN12);
    cudaFuncSetAttribute(gemm3,  cudaFuncAttributeMaxDynamicSharedMemorySize, DYN3);
    (void)attr_set;

    {
        dim3 grid(I_DIM / 128, T_TOK / 128);   // 32 x 64
        gemm12<<<grid, 256, DYN12>>>(x, gate_w, up_w, gate_b, up_b, offs, pact);
    }
    {
        dim3 grid(H_DIM / 128, T_TOK / 128);   // 16 x 64
        gemm3<<<grid, 256, DYN3>>>(pact, down_w, down_b, offs, out);
    }
}

// round 5
// speedup vs baseline: 3.3527x; 1.0484x over previous
#include <cuda_runtime.h>
#include <cstdint>

#define T_TOK 8192
#define H_DIM 2048
#define I_DIM 4096
#define E_NUM 8
#define SWIGLU_ALPHA 1.702f
#define SWIGLU_LIMIT 7.0f

// Scratch: tf32-pre-rounded operands + activated intermediate
__device__ float g_x[(size_t)T_TOK * H_DIM];
__device__ float g_act[(size_t)T_TOK * I_DIM];
__device__ float g_wg[(size_t)E_NUM * H_DIM * I_DIM];
__device__ float g_wu[(size_t)E_NUM * H_DIM * I_DIM];
__device__ float g_wd[(size_t)E_NUM * I_DIM * H_DIM];

// ---------------------------------------------------------------------------
// Helpers
// ---------------------------------------------------------------------------
__device__ __forceinline__ uint32_t smem_u32(const void* p) {
    uint32_t a;
    asm("{ .reg .u64 t; cvta.to.shared.u64 t, %1; cvt.u32.u64 %0, t; }" : "=r"(a) : "l"(p));
    return a;
}
__device__ __forceinline__ float tf32r(float v) {
    float r;
    asm("cvt.rna.tf32.f32 %0, %1;" : "=f"(r) : "f"(v));
    return r;
}
// Operands are pre-rounded to tf32; pass raw fp32 bits (HW ignores low mantissa)
__device__ __forceinline__ void mma8(float c[4],
                                     uint32_t a0, uint32_t a1, uint32_t a2, uint32_t a3,
                                     uint32_t b0, uint32_t b1) {
    asm("mma.sync.aligned.m16n8k8.row.col.f32.tf32.tf32.f32 "
        "{%0,%1,%2,%3}, {%4,%5,%6,%7}, {%8,%9}, {%0,%1,%2,%3};"
        : "+f"(c[0]), "+f"(c[1]), "+f"(c[2]), "+f"(c[3])
        : "r"(a0), "r"(a1), "r"(a2), "r"(a3), "r"(b0), "r"(b1));
}
#define CP16(dst, src) \
    asm volatile("cp.async.cg.shared.global [%0], [%1], 16;" :: "r"(dst), "l"(src))
#define CP_COMMIT() asm volatile("cp.async.commit_group;")
#define CP_WAIT1()  asm volatile("cp.async.wait_group 1;")

__device__ __forceinline__ float swiglu(float g, float u) {
    g = fminf(g, SWIGLU_LIMIT);
    u = fminf(fmaxf(u, -SWIGLU_LIMIT), SWIGLU_LIMIT);
    float sig = 1.0f / (1.0f + __expf(-SWIGLU_ALPHA * g));
    return (u + 1.0f) * g * sig;
}
__device__ __forceinline__ uint32_t ldsf(const float* p) {
    return __float_as_uint(*p);
}

constexpr int APAD = 36;     // bank = (4r + c) % 32 -> conflict-free
constexpr int ABYTES = 128 * APAD * 4;         // 18432

// ===========================================================================
// Staging: RN-round a stream to tf32 (values stay valid fp32)
// ===========================================================================
__global__ __launch_bounds__(256) void round_kernel(const float4* __restrict__ in,
                                                    float4* __restrict__ out, int n4) {
    int i = blockIdx.x * 256 + threadIdx.x;
    if (i >= n4) return;
    float4 v = in[i];
    v.x = tf32r(v.x); v.y = tf32r(v.y); v.z = tf32r(v.z); v.w = tf32r(v.w);
    out[i] = v;
}

// ===========================================================================
// Fused gate+up GEMM + bias + swiglu -> g_act (tf32-rounded)
// CTA 128 x 128 (both gate and up), BK=32, 8 warps (2x4), warp 64x32 x2
// ===========================================================================
constexpr int BPAD12 = 136;
constexpr int BBYTES12 = 32 * BPAD12 * 4;      // 17408
constexpr int STG12 = 3;
constexpr int STAGE12 = ABYTES + 2 * BBYTES12; // 53248
constexpr int DYN12 = STG12 * STAGE12;         // 159744

__global__ __launch_bounds__(256, 1)
void gemm12(const float* __restrict__ x,
            const float* __restrict__ gw,
            const float* __restrict__ uw,
            const float* __restrict__ gb,
            const float* __restrict__ ub,
            const int* __restrict__ offs,
            float* __restrict__ act)
{
    extern __shared__ float sm[];
    const uint32_t sbase = smem_u32(sm);
    const int tid = threadIdx.x, lane = tid & 31, warp = tid >> 5;
    const int wm = warp >> 2, wn = warp & 3;
    const int gid = lane >> 2, tig = lane & 3;
    const int n0 = blockIdx.x * 128, m0 = blockIdx.y * 128;

    int e = 0;
#pragma unroll
    for (int i = 0; i < E_NUM - 1; i++)
        if (m0 >= offs[i]) e = i + 1;

    const float* xa  = x + (size_t)m0 * H_DIM;
    const float* gwa = gw + (size_t)e * H_DIM * I_DIM + n0;
    const float* uwa = uw + (size_t)e * H_DIM * I_DIM + n0;

    auto issue = [&](int it, int s) {
        const uint32_t sa = sbase + s * STAGE12;
        const int k0 = it * 32;
#pragma unroll
        for (int j = 0; j < 4; j++) {
            int idx = tid + 256 * j;
            int r = idx >> 3, c4 = idx & 7;
            CP16(sa + (uint32_t)(r * APAD + c4 * 4) * 4,
                 xa + (size_t)r * H_DIM + k0 + c4 * 4);
        }
        const uint32_t sg = sa + ABYTES, su = sa + ABYTES + BBYTES12;
#pragma unroll
        for (int j = 0; j < 4; j++) {
            int idx = tid + 256 * j;
            int r = idx >> 5, c4 = idx & 31;
            uint32_t off = (uint32_t)(r * BPAD12 + c4 * 4) * 4;
            CP16(sg + off, gwa + (size_t)(k0 + r) * I_DIM + c4 * 4);
            CP16(su + off, uwa + (size_t)(k0 + r) * I_DIM + c4 * 4);
        }
        CP_COMMIT();
    };

    float cg[4][4][4] = {}, cu[4][4][4] = {};

    issue(0, 0);
    issue(1, 1);

    const int NIT = H_DIM / 32;   // 64
    for (int it = 0; it < NIT; ++it) {
        const int s = it % STG12;
        CP_WAIT1();
        __syncthreads();

        const float* A  = sm + s * (STAGE12 / 4);
        const float* Bg = A + ABYTES / 4;
        const float* Bu = Bg + BBYTES12 / 4;

#pragma unroll
        for (int ks = 0; ks < 4; ++ks) {
            uint32_t a[4][4];
#pragma unroll
            for (int mf = 0; mf < 4; mf++) {
                const float* ap = A + (wm * 64 + mf * 16 + gid) * APAD + ks * 8 + tig;
                a[mf][0] = ldsf(ap);
                a[mf][1] = ldsf(ap + 8 * APAD);
                a[mf][2] = ldsf(ap + 4);
                a[mf][3] = ldsf(ap + 8 * APAD + 4);
            }
#pragma unroll
            for (int nf = 0; nf < 4; nf++) {
                const int c = wn * 32 + nf * 8 + gid;
                const float* bp = Bg + (ks * 8 + tig) * BPAD12 + c;
                uint32_t b0 = ldsf(bp), b1 = ldsf(bp + 4 * BPAD12);
                const float* up = Bu + (ks * 8 + tig) * BPAD12 + c;
                uint32_t u0 = ldsf(up), u1 = ldsf(up + 4 * BPAD12);
#pragma unroll
                for (int mf = 0; mf < 4; mf++) {
                    mma8(cg[mf][nf], a[mf][0], a[mf][1], a[mf][2], a[mf][3], b0, b1);
                    mma8(cu[mf][nf], a[mf][0], a[mf][1], a[mf][2], a[mf][3], u0, u1);
                }
            }
        }
        if (it + 2 < NIT) issue(it + 2, (it + 2) % STG12);
        else CP_COMMIT();
    }

    // Epilogue: bias + swiglu -> act (tf32-rounded so gemm3 can skip cvt)
#pragma unroll
    for (int nf = 0; nf < 4; nf++) {
        const int c0 = n0 + wn * 32 + nf * 8 + 2 * tig;
        const float2 gbv = *reinterpret_cast<const float2*>(gb + (size_t)e * I_DIM + c0);
        const float2 ubv = *reinterpret_cast<const float2*>(ub + (size_t)e * I_DIM + c0);
#pragma unroll
        for (int mf = 0; mf < 4; mf++) {
            const int r0 = m0 + wm * 64 + mf * 16 + gid;
            float2 o0, o1;
            o0.x = tf32r(swiglu(cg[mf][nf][0] + gbv.x, cu[mf][nf][0] + ubv.x));
            o0.y = tf32r(swiglu(cg[mf][nf][1] + gbv.y, cu[mf][nf][1] + ubv.y));
            o1.x = tf32r(swiglu(cg[mf][nf][2] + gbv.x, cu[mf][nf][2] + ubv.x));
            o1.y = tf32r(swiglu(cg[mf][nf][3] + gbv.y, cu[mf][nf][3] + ubv.y));
            *reinterpret_cast<float2*>(act + (size_t)r0 * I_DIM + c0) = o0;
            *reinterpret_cast<float2*>(act + (size_t)(r0 + 8) * I_DIM + c0) = o1;
        }
    }
}

// ===========================================================================
// Down GEMM + bias -> out. CTA 128 x 256, BK=32, 8 warps (2x4), warp 64x64
// ===========================================================================
constexpr int BPAD3 = 264;
constexpr int BBYTES3 = 32 * BPAD3 * 4;        // 33792
constexpr int STG3 = 3;
constexpr int STAGE3 = ABYTES + BBYTES3;       // 52224
constexpr int DYN3 = STG3 * STAGE3;            // 156672

__global__ __launch_bounds__(256, 1)
void gemm3(const float* __restrict__ act,
           const float* __restrict__ dw,
           const float* __restrict__ db,
           const int* __restrict__ offs,
           float* __restrict__ out)
{
    extern __shared__ float sm[];
    const uint32_t sbase = smem_u32(sm);
    const int tid = threadIdx.x, lane = tid & 31, warp = tid >> 5;
    const int wm = warp >> 2, wn = warp & 3;
    const int gid = lane >> 2, tig = lane & 3;
    const int n0 = blockIdx.x * 256, m0 = blockIdx.y * 128;

    int e = 0;
#pragma unroll
    for (int i = 0; i < E_NUM - 1; i++)
        if (m0 >= offs[i]) e = i + 1;

    const float* aa  = act + (size_t)m0 * I_DIM;
    const float* dwa = dw + (size_t)e * I_DIM * H_DIM + n0;

    auto issue = [&](int it, int s) {
        const uint32_t sa = sbase + s * STAGE3;
        const int k0 = it * 32;
#pragma unroll
        for (int j = 0; j < 4; j++) {
            int idx = tid + 256 * j;
            int r = idx >> 3, c4 = idx & 7;
            CP16(sa + (uint32_t)(r * APAD + c4 * 4) * 4,
                 aa + (size_t)r * I_DIM + k0 + c4 * 4);
        }
        const uint32_t sb = sa + ABYTES;
#pragma unroll
        for (int j = 0; j < 8; j++) {
            int idx = tid + 256 * j;
            int r = idx >> 6, c4 = idx & 63;
            CP16(sb + (uint32_t)(r * BPAD3 + c4 * 4) * 4,
                 dwa + (size_t)(k0 + r) * H_DIM + c4 * 4);
        }
        CP_COMMIT();
    };

    float cc[4][8][4] = {};

    issue(0, 0);
    issue(1, 1);

    const int NIT = I_DIM / 32;   // 128
    for (int it = 0; it < NIT; ++it) {
        const int s = it % STG3;
        CP_WAIT1();
        __syncthreads();

        const float* A = sm + s * (STAGE3 / 4);
        const float* B = A + ABYTES / 4;

#pragma unroll
        for (int ks = 0; ks < 4; ++ks) {
            uint32_t a[4][4];
#pragma unroll
            for (int mf = 0; mf < 4; mf++) {
                const float* ap = A + (wm * 64 + mf * 16 + gid) * APAD + ks * 8 + tig;
                a[mf][0] = ldsf(ap);
                a[mf][1] = ldsf(ap + 8 * APAD);
                a[mf][2] = ldsf(ap + 4);
                a[mf][3] = ldsf(ap + 8 * APAD + 4);
            }
#pragma unroll
            for (int nf = 0; nf < 8; nf++) {
                const int c = wn * 64 + nf * 8 + gid;
                const float* bp = B + (ks * 8 + tig) * BPAD3 + c;
                uint32_t b0 = ldsf(bp), b1 = ldsf(bp + 4 * BPAD3);
#pragma unroll
                for (int mf = 0; mf < 4; mf++)
                    mma8(cc[mf][nf], a[mf][0], a[mf][1], a[mf][2], a[mf][3], b0, b1);
            }
        }
        if (it + 2 < NIT) issue(it + 2, (it + 2) % STG3);
        else CP_COMMIT();
    }

    // Epilogue: + down_b -> out
#pragma unroll
    for (int nf = 0; nf < 8; nf++) {
        const int c0 = n0 + wn * 64 + nf * 8 + 2 * tig;
        const float2 bv = *reinterpret_cast<const float2*>(db + (size_t)e * H_DIM + c0);
#pragma unroll
        for (int mf = 0; mf < 4; mf++) {
            const int r0 = m0 + wm * 64 + mf * 16 + gid;
            float2 o0, o1;
            o0.x = cc[mf][nf][0] + bv.x;
            o0.y = cc[mf][nf][1] + bv.y;
            o1.x = cc[mf][nf][2] + bv.x;
            o1.y = cc[mf][nf][3] + bv.y;
            *reinterpret_cast<float2*>(out + (size_t)r0 * H_DIM + c0) = o0;
            *reinterpret_cast<float2*>(out + (size_t)(r0 + 8) * H_DIM + c0) = o1;
        }
    }
}

// ===========================================================================
// Launch
// ===========================================================================
extern "C" void kernel_launch(void* const* d_in, const int* in_sizes, int n_in,
                              void* d_out, int out_size)
{
    const float* x      = (const float*)d_in[0];
    const int*   offs   = (const int*)d_in[1];
    const float* gate_w = (const float*)d_in[2];
    const float* up_w   = (const float*)d_in[3];
    const float* down_w = (const float*)d_in[4];
    const float* gate_b = (const float*)d_in[5];
    const float* up_b   = (const float*)d_in[6];
    const float* down_b = (const float*)d_in[7];
    float* out = (float*)d_out;

    float *px, *pact, *pwg, *pwu, *pwd;
    cudaGetSymbolAddress((void**)&px,   g_x);
    cudaGetSymbolAddress((void**)&pact, g_act);
    cudaGetSymbolAddress((void**)&pwg,  g_wg);
    cudaGetSymbolAddress((void**)&pwu,  g_wu);
    cudaGetSymbolAddress((void**)&pwd,  g_wd);

    cudaFuncSetAttribute(gemm12, cudaFuncAttributeMaxDynamicSharedMemorySize, DYN12);
    cudaFuncSetAttribute(gemm3,  cudaFuncAttributeMaxDynamicSharedMemorySize, DYN3);

    // Staging: RN-round operands to tf32 so GEMMs skip in-loop cvt
    {
        int n4 = T_TOK * H_DIM / 4;
        round_kernel<<<(n4 + 255) / 256, 256>>>((const float4*)x, (float4*)px, n4);
    }
    {
        int n4 = E_NUM * H_DIM * I_DIM / 4;   // 16Mi float4
        round_kernel<<<(n4 + 255) / 256, 256>>>((const float4*)gate_w, (float4*)pwg, n4);
        round_kernel<<<(n4 + 255) / 256, 256>>>((const float4*)up_w,   (float4*)pwu, n4);
        round_kernel<<<(n4 + 255) / 256, 256>>>((const float4*)down_w, (float4*)pwd, n4);
    }
    {
        dim3 grid(I_DIM / 128, T_TOK / 128);   // 32 x 64
        gemm12<<<grid, 256, DYN12>>>(px, pwg, pwu, gate_b, up_b, offs, pact);
    }
    {
        dim3 grid(H_DIM / 256, T_TOK / 128);   // 8 x 64
        gemm3<<<grid, 256, DYN3>>>(pact, pwd, down_b, offs, out);
    }
}